// round 12
// baseline (speedup 1.0000x reference)
#include <cuda_runtime.h>

// LengthRegulator, single fused kernel, 64-frame tiles + windowed scatter +
// zero-block early-out.
// out[b, t, :] = x[b, j, :] where token j owns frame t (cum[j-1] <= t < cum[j]);
// zero for t >= cum[L-1]. Second output: durations echoed as float.
// Shapes: N=16, L=512, D=384, T=3584.

#define NB 16
#define LL 512
#define DD 384
#define V4 (DD / 4)                 // 96 float4 per frame
#define GROUPS 8                    // 96-lane groups per block
#define FPT 8                       // frames per thread
#define TILE (GROUPS * FPT)         // 64 frames per block
#define THREADS (V4 * GROUPS)       // 768

__global__ void __launch_bounds__(THREADS)
lr_fused_kernel(const float* __restrict__ x,
                const int* __restrict__ dur,
                float* __restrict__ out,
                float* __restrict__ echo_dst, int T) {
    __shared__ int sdur[LL];        // 2 KB
    __shared__ int sidx[TILE];      // this block's 64 frame->token entries
    __shared__ int swsum[4];        // chunk-warp sums

    const int b = blockIdx.y;
    const int tid = threadIdx.x;
    const int t0 = blockIdx.x * TILE;
    const int t1 = t0 + TILE;

    // ---- stage dur row (512 ints with 768 threads) ----
    if (tid < LL) sdur[tid] = dur[b * LL + tid];
    __syncthreads();

    // ---- phase 1: chunk sums + warp totals (threads 0..127, 4 tokens each) ----
    int a0, a1, a2, a3, s3 = 0, inc = 0;
    if (tid < 128) {
        const int base = tid * 4;
        a0 = sdur[base + 0];
        a1 = sdur[base + 1];
        a2 = sdur[base + 2];
        a3 = sdur[base + 3];
        s3 = a0 + a1 + a2 + a3;

        inc = s3;                                 // inclusive warp scan of chunk sums
        const int lane = tid & 31;
#pragma unroll
        for (int off = 1; off < 32; off <<= 1) {
            int v = __shfl_up_sync(0xffffffffu, inc, off);
            if (lane >= off) inc += v;
        }
        if (lane == 31) swsum[tid >> 5] = inc;    // warp total
    }
    __syncthreads();

    const int total = swsum[0] + swsum[1] + swsum[2] + swsum[3];

    // ---- phase 2: windowed scatter (skipped entirely for pure-zero blocks) ----
    if (t0 < total && tid < 128) {
        const int w = tid >> 5;
        int wexcl = 0;
#pragma unroll
        for (int k = 0; k < 3; ++k)
            if (k < w) wexcl += swsum[k];

        int c = inc - s3 + wexcl;                 // exclusive prefix before chunk
        const int base = tid * 4;
        const int ds[4] = {a0, a1, a2, a3};
#pragma unroll
        for (int k = 0; k < 4; ++k) {
            const int d = ds[k];
            const int lo = (c > t0) ? c : t0;     // overlap with [t0, t1)
            const int hi = (c + d < t1) ? c + d : t1;
            for (int i = lo; i < hi; ++i)
                sidx[i - t0] = base + k;
            c += d;
        }
    }

    // ---- echo durations (only the x==0 blocks; 16 total) ----
    if (blockIdx.x == 0 && echo_dst && tid < LL)
        echo_dst[b * LL + tid] = (float)sdur[tid];
    __syncthreads();

    // ---- gather/store: 8-frame ILP body ----
    const int g = tid / V4;                       // 0..7
    const int v = tid % V4;                       // 0..95
    const int tf = t0 + g * FPT;                  // first of this thread's 8 frames

    int js[FPT];
#pragma unroll
    for (int k = 0; k < FPT; ++k)
        js[k] = sidx[g * FPT + k];                // broadcast across 96-lane group

    const float4* xb = reinterpret_cast<const float4*>(x + (size_t)b * LL * DD);

    float4 val[FPT];
#pragma unroll
    for (int k = 0; k < FPT; ++k) {
        val[k] = make_float4(0.f, 0.f, 0.f, 0.f);
        if (tf + k < total)
            val[k] = xb[(size_t)js[k] * V4 + v];  // 8 independent gathers
    }

    float4* ob = reinterpret_cast<float4*>(out + ((size_t)b * T + tf) * DD);
#pragma unroll
    for (int k = 0; k < FPT; ++k)
        __stcs(&ob[(size_t)k * V4 + v], val[k]);  // streaming coalesced stores
}

extern "C" void kernel_launch(void* const* d_in, const int* in_sizes, int n_in,
                              void* d_out, int out_size) {
    const float* x = (const float*)d_in[0];
    const int* dur = (const int*)d_in[1];

    const int NL = NB * LL;                          // 8192
    const long long per_frame = (long long)NB * DD;  // 6144 elems per time step

    long long main_elems = out_size;
    float* echo_dst = nullptr;
    if (main_elems % per_frame != 0) {
        main_elems -= NL;
        echo_dst = (float*)d_out + main_elems;
    }
    const int T = (int)(main_elems / per_frame);     // 3584

    dim3 grid(T / TILE, NB);                         // 56 x 16 = 896 blocks
    lr_fused_kernel<<<grid, THREADS>>>(x, dur, (float*)d_out, echo_dst, T);
}

// round 13
// speedup vs baseline: 1.1825x; 1.1825x over previous
#include <cuda_runtime.h>

// LengthRegulator, single fused kernel (TILE=32, registers-only prep).
// out[b, t, :] = x[b, j, :] where token j owns frame t (cum[j-1] <= t < cum[j]);
// zero for t >= cum[L-1]. Second output: durations echoed as float.
// Shapes: N=16, L=512, D=384, T=3584.

#define NB 16
#define LL 512
#define DD 384
#define V4 (DD / 4)                 // 96 float4 per frame
#define GROUPS 4                    // 96-lane groups per block
#define FPT 8                       // frames per thread
#define TILE (GROUPS * FPT)         // 32 frames per block
#define THREADS (V4 * GROUPS)       // 384

__global__ void __launch_bounds__(THREADS)
lr_fused_kernel(const float* __restrict__ x,
                const int* __restrict__ dur,
                float* __restrict__ out,
                float* __restrict__ echo_dst, int T) {
    __shared__ int sidx[TILE];      // this block's 32 frame->token entries
    __shared__ int swsum[4];        // chunk-warp sums

    const int b = blockIdx.y;
    const int tid = threadIdx.x;
    const int t0 = blockIdx.x * TILE;
    const int t1 = t0 + TILE;

    // ---- phase 1: threads 0..127 each own 4 tokens (one coalesced int4) ----
    int a0 = 0, a1 = 0, a2 = 0, a3 = 0, s3 = 0, inc = 0;
    if (tid < 128) {
        const int4 d4 = *reinterpret_cast<const int4*>(&dur[b * LL + tid * 4]);
        a0 = d4.x; a1 = d4.y; a2 = d4.z; a3 = d4.w;
        s3 = a0 + a1 + a2 + a3;

        inc = s3;                                 // inclusive warp scan of chunk sums
        const int lane = tid & 31;
#pragma unroll
        for (int off = 1; off < 32; off <<= 1) {
            int v = __shfl_up_sync(0xffffffffu, inc, off);
            if (lane >= off) inc += v;
        }
        if (lane == 31) swsum[tid >> 5] = inc;    // warp total

        // echo durations straight from registers (16 blocks only)
        if (blockIdx.x == 0 && echo_dst) {
            float4 e = make_float4((float)a0, (float)a1, (float)a2, (float)a3);
            *reinterpret_cast<float4*>(&echo_dst[b * LL + tid * 4]) = e;
        }
    }
    __syncthreads();

    const int total = swsum[0] + swsum[1] + swsum[2] + swsum[3];

    // ---- phase 2: windowed scatter (skipped for pure-zero blocks) ----
    if (t0 < total && tid < 128) {
        const int w = tid >> 5;
        int wexcl = 0;
#pragma unroll
        for (int k = 0; k < 3; ++k)
            if (k < w) wexcl += swsum[k];

        int c = inc - s3 + wexcl;                 // exclusive prefix before chunk
        const int base = tid * 4;
        const int ds[4] = {a0, a1, a2, a3};
#pragma unroll
        for (int k = 0; k < 4; ++k) {
            const int d = ds[k];
            const int lo = (c > t0) ? c : t0;     // overlap with [t0, t1)
            const int hi = (c + d < t1) ? c + d : t1;
            for (int i = lo; i < hi; ++i)
                sidx[i - t0] = base + k;
            c += d;
        }
    }
    __syncthreads();

    // ---- gather/store: 8-frame ILP body ----
    const int g = tid / V4;                       // 0..3
    const int v = tid % V4;                       // 0..95
    const int tf = t0 + g * FPT;                  // first of this thread's 8 frames

    int js[FPT];
#pragma unroll
    for (int k = 0; k < FPT; ++k)
        js[k] = sidx[g * FPT + k];                // broadcast across 96-lane group

    const float4* xb = reinterpret_cast<const float4*>(x + (size_t)b * LL * DD);

    float4 val[FPT];
#pragma unroll
    for (int k = 0; k < FPT; ++k) {
        val[k] = make_float4(0.f, 0.f, 0.f, 0.f);
        if (tf + k < total)
            val[k] = xb[(size_t)js[k] * V4 + v];  // 8 independent gathers
    }

    float4* ob = reinterpret_cast<float4*>(out + ((size_t)b * T + tf) * DD);
#pragma unroll
    for (int k = 0; k < FPT; ++k)
        __stcs(&ob[(size_t)k * V4 + v], val[k]);  // streaming coalesced stores
}

extern "C" void kernel_launch(void* const* d_in, const int* in_sizes, int n_in,
                              void* d_out, int out_size) {
    const float* x = (const float*)d_in[0];
    const int* dur = (const int*)d_in[1];

    const int NL = NB * LL;                          // 8192
    const long long per_frame = (long long)NB * DD;  // 6144 elems per time step

    long long main_elems = out_size;
    float* echo_dst = nullptr;
    if (main_elems % per_frame != 0) {
        main_elems -= NL;
        echo_dst = (float*)d_out + main_elems;
    }
    const int T = (int)(main_elems / per_frame);     // 3584

    dim3 grid(T / TILE, NB);                         // 112 x 16 = 1792 blocks
    lr_fused_kernel<<<grid, THREADS>>>(x, dur, (float*)d_out, echo_dst, T);
}